// round 2
// baseline (speedup 1.0000x reference)
#include <cuda_runtime.h>
#include <math.h>

// Problem constants (fixed shapes per reference).
#define B_SZ   16384
#define G_SZ   256
#define NROWS  (B_SZ * G_SZ)          // 4,194,304 (b,g) rows
#define CLS_ROWS 8192                 // first batch_size flat elems -> rows < 8192
#define INV_B  (1.0f / 16384.0f)

__global__ void zero_out_kernel(float* __restrict__ out) {
    out[0] = 0.0f;
}

__global__ __launch_bounds__(256)
void ensemble_loss_kernel(const float4* __restrict__ pred4,
                          const float4* __restrict__ targ4,
                          float* __restrict__ out) {
    const int tid    = blockIdx.x * blockDim.x + threadIdx.x;
    const int stride = gridDim.x * blockDim.x;

    float acc = 0.0f;

    for (int r = tid; r < NROWS; r += stride) {
        // pred row: 12 floats = 3x float4 (48B, 16B-aligned per row)
        const float4 p0 = pred4[(long long)r * 3 + 0]; // f0..f3 : off0,dur0,conf0,cls0_0
        const float4 p1 = pred4[(long long)r * 3 + 1]; // f4..f7 : cls0_1,cls0_2,off1,dur1
        const float4 p2 = pred4[(long long)r * 3 + 2]; // f8..f11: conf1,cls1_0,cls1_1,cls1_2
        // target row: 8 floats = 2x float4
        const float4 t0 = targ4[(long long)r * 2 + 0]; // conf0,cls0,off0,dur0
        const float4 t1 = targ4[(long long)r * 2 + 1]; // conf1,cls1,off1,dur1

        // ---------- anchor 0 ----------
        {
            const float gc  = t0.x;              // in {0,1}: obj_mask == gc
            const float w   = 0.5f + 0.5f * gc;  // 1 if obj, 0.5 if noobj
            const float dc  = gc - p0.z;
            acc += w * dc * dc;

            const float doff = t0.z - p0.x;
            acc += 5.0f * gc * doff * doff;

            const float dd = sqrtf(t0.w) - sqrtf(p0.y);
            acc += 5.0f * gc * dd * dd;

            if (r < CLS_ROWS) {
                const float l0 = gc * p0.w;
                const float l1 = gc * p1.x;
                const float l2 = gc * p1.y;
                const int   idx = (int)(gc * t0.y);
                const float m  = fmaxf(l0, fmaxf(l1, l2));
                const float lse = m + logf(expf(l0 - m) + expf(l1 - m) + expf(l2 - m));
                const float li = (idx == 0) ? l0 : ((idx == 1) ? l1 : l2);
                acc += lse - li;
            }
        }

        // ---------- anchor 1 ----------
        {
            const float gc  = t1.x;
            const float w   = 0.5f + 0.5f * gc;
            const float dc  = gc - p2.x;
            acc += w * dc * dc;

            const float doff = t1.z - p1.z;
            acc += 5.0f * gc * doff * doff;

            const float dd = sqrtf(t1.w) - sqrtf(p1.w);
            acc += 5.0f * gc * dd * dd;

            if (r < CLS_ROWS) {
                const float l0 = gc * p2.y;
                const float l1 = gc * p2.z;
                const float l2 = gc * p2.w;
                const int   idx = (int)(gc * t1.y);
                const float m  = fmaxf(l0, fmaxf(l1, l2));
                const float lse = m + logf(expf(l0 - m) + expf(l1 - m) + expf(l2 - m));
                const float li = (idx == 0) ? l0 : ((idx == 1) ? l1 : l2);
                acc += lse - li;
            }
        }
    }

    // ---- intra-warp reduction ----
    #pragma unroll
    for (int off = 16; off > 0; off >>= 1)
        acc += __shfl_down_sync(0xffffffffu, acc, off);

    // ---- intra-block reduction ----
    __shared__ float smem[8];
    const int lane = threadIdx.x & 31;
    const int warp = threadIdx.x >> 5;
    if (lane == 0) smem[warp] = acc;
    __syncthreads();
    if (warp == 0) {
        acc = (lane < (blockDim.x >> 5)) ? smem[lane] : 0.0f;
        #pragma unroll
        for (int off = 4; off > 0; off >>= 1)
            acc += __shfl_down_sync(0xffffffffu, acc, off);
        if (lane == 0)
            atomicAdd(out, acc * INV_B);
    }
}

extern "C" void kernel_launch(void* const* d_in, const int* in_sizes, int n_in,
                              void* d_out, int out_size) {
    const float4* pred4 = (const float4*)d_in[0];
    const float4* targ4 = (const float4*)d_in[1];
    float* out = (float*)d_out;

    zero_out_kernel<<<1, 1>>>(out);

    const int threads = 256;
    const int blocks  = 8192;   // 2.1M threads, ~2 rows/thread, fills 148 SMs
    ensemble_loss_kernel<<<blocks, threads>>>(pred4, targ4, out);
}